// round 4
// baseline (speedup 1.0000x reference)
#include <cuda_runtime.h>
#include <cstdint>

// scGNN: 2-layer GCN on GB300.
//   deg = indegree(dst)+1 ; dinv = rsqrt(deg) ; norm(e) = dinv[src]*dinv[dst]
//   L1: h1 = x@W1 ; a1 = scatter_add(h1[src]*norm -> dst) + self ; r = relu(a1+b1)
//   L2: h2 = r@W2 ; out = scatter_add(h2[src]*norm -> dst) + self + b2
//
// edge_index arrives as int32 (JAX x64-disabled downcasts jnp.int64).
// A tiny detection kernel confirms at runtime and the edge kernels branch
// on a uniform flag, so both dtypes are handled without host-side sync.

#define NN   100000
#define FIN  64
#define FMID 32

// Scratch (static device arrays are allowed; cudaMalloc is not).
static __device__ int   g_is64;
static __device__ __align__(16) float g_dinv[NN];
static __device__ __align__(16) float g_h1[NN * FMID];   // x @ W1
static __device__ __align__(16) float g_a1[NN * FMID];   // layer-1 aggregate
static __device__ __align__(16) float g_h2[NN * FIN];    // relu(a1+b1) @ W2
static __device__ __align__(16) float g_out[NN * FIN];   // layer-2 aggregate

// ---------------------------------------------------------------------------
// Edge-index accessor: uniform branch on detected dtype + clamp (safety:
// a bad index becomes a wrong answer, never an address-space trap).
__device__ __forceinline__ int get_idx(const void* ei, int pos) {
    int v = g_is64 ? (int)((const long long*)ei)[pos]
                   : ((const int*)ei)[pos];
    return min(max(v, 0), NN - 1);
}

// Detect int64-vs-int32: int64 values < 2^31 have all-zero high words.
__global__ void k_detect(const int* __restrict__ ei) {
    __shared__ int nz;
    if (threadIdx.x == 0) nz = 0;
    __syncthreads();
    for (int i = threadIdx.x; i < 2048; i += blockDim.x)
        if (ei[2 * i + 1] != 0) nz = 1;
    __syncthreads();
    if (threadIdx.x == 0) g_is64 = (nz == 0) ? 1 : 0;
}

// ---------------------------------------------------------------------------
__global__ void k_deg_init(int n) {
    int i = blockIdx.x * blockDim.x + threadIdx.x;
    if (i < n) g_dinv[i] = 1.0f;   // self-loop contributes 1 to in-degree
}

__global__ void k_deg_count(const void* __restrict__ ei, int E) {
    int i = blockIdx.x * blockDim.x + threadIdx.x;
    if (i < E) atomicAdd(&g_dinv[get_idx(ei, E + i)], 1.0f);
}

__global__ void k_deg_finalize(int n) {
    int i = blockIdx.x * blockDim.x + threadIdx.x;
    if (i < n) g_dinv[i] = rsqrtf(g_dinv[i]);
}

// ---------------------------------------------------------------------------
// GEMM1: g_h1[N,32] = x[N,64] @ W1[64,32]. One warp per row, lane = out col.
__global__ void k_gemm1(const float* __restrict__ x,
                        const float* __restrict__ W1, int n) {
    __shared__ float sW[FIN * FMID];  // 8 KB
    for (int i = threadIdx.x; i < FIN * FMID; i += blockDim.x)
        sW[i] = W1[i];
    __syncthreads();

    int warp = threadIdx.x >> 5;
    int lane = threadIdx.x & 31;
    int row  = blockIdx.x * 8 + warp;
    if (row >= n) return;

    float xa = x[row * FIN + lane];
    float xb = x[row * FIN + 32 + lane];
    float acc = 0.0f;
#pragma unroll
    for (int k = 0; k < 32; k++)
        acc += __shfl_sync(0xffffffffu, xa, k) * sW[k * FMID + lane];
#pragma unroll
    for (int k = 0; k < 32; k++)
        acc += __shfl_sync(0xffffffffu, xb, k) * sW[(k + 32) * FMID + lane];
    g_h1[row * FMID + lane] = acc;
}

// a1 := self-loop term (dinv_i^2 * h1_i). Full overwrite -> no memset needed.
__global__ void k_a1_init(int n) {
    int idx = blockIdx.x * blockDim.x + threadIdx.x;
    if (idx < n * FMID) {
        int i  = idx >> 5;
        float di = g_dinv[i];
        g_a1[idx] = di * di * g_h1[idx];
    }
}

// Layer-1 edge scatter: 8 threads/edge; each gathers a float4 and issues
// 4 scalar atomics.
__global__ void k_scatter1(const void* __restrict__ ei, int E) {
    int t = blockIdx.x * blockDim.x + threadIdx.x;
    if (t >= E * 8) return;
    int e = t >> 3;
    int q = (t & 7) * 4;
    int s = get_idx(ei, e);
    int d = get_idx(ei, E + e);
    float norm = g_dinv[s] * g_dinv[d];
    const float4 v = *reinterpret_cast<const float4*>(&g_h1[s * FMID + q]);
    float* o = &g_a1[d * FMID + q];
    atomicAdd(o + 0, v.x * norm);
    atomicAdd(o + 1, v.y * norm);
    atomicAdd(o + 2, v.z * norm);
    atomicAdd(o + 3, v.w * norm);
}

// ---------------------------------------------------------------------------
// GEMM2 (fused relu+bias): g_h2[N,64] = relu(a1+b1)[N,32] @ W2[32,64].
// One warp per row; lane owns out cols {lane, lane+32}; a_k via shuffle.
__global__ void k_gemm2(const float* __restrict__ b1,
                        const float* __restrict__ W2, int n) {
    __shared__ float sW[FMID * FIN];  // 8 KB
    for (int i = threadIdx.x; i < FMID * FIN; i += blockDim.x)
        sW[i] = W2[i];
    __syncthreads();

    int warp = threadIdx.x >> 5;
    int lane = threadIdx.x & 31;
    int row  = blockIdx.x * 8 + warp;
    if (row >= n) return;

    float a = fmaxf(g_a1[row * FMID + lane] + b1[lane], 0.0f);
    float acc0 = 0.0f, acc1 = 0.0f;
#pragma unroll
    for (int k = 0; k < 32; k++) {
        float ak = __shfl_sync(0xffffffffu, a, k);
        acc0 += ak * sW[k * FIN + lane];
        acc1 += ak * sW[k * FIN + 32 + lane];
    }
    g_h2[row * FIN + lane]      = acc0;
    g_h2[row * FIN + 32 + lane] = acc1;
}

// g_out := b2 + self-loop term (full overwrite of scratch).
__global__ void k_out_init(const float* __restrict__ b2, int n) {
    int idx = blockIdx.x * blockDim.x + threadIdx.x;
    if (idx < n * FIN) {
        int i = idx >> 6;
        int c = idx & 63;
        float di = g_dinv[i];
        g_out[idx] = b2[c] + di * di * g_h2[idx];
    }
}

// Layer-2 edge scatter: 16 threads/edge, 4 floats each, into own scratch.
__global__ void k_scatter2(const void* __restrict__ ei, int E) {
    int t = blockIdx.x * blockDim.x + threadIdx.x;
    if (t >= E * 16) return;
    int e = t >> 4;
    int q = (t & 15) * 4;
    int s = get_idx(ei, e);
    int d = get_idx(ei, E + e);
    float norm = g_dinv[s] * g_dinv[d];
    const float4 v = *reinterpret_cast<const float4*>(&g_h2[s * FIN + q]);
    float* o = &g_out[d * FIN + q];
    atomicAdd(o + 0, v.x * norm);
    atomicAdd(o + 1, v.y * norm);
    atomicAdd(o + 2, v.z * norm);
    atomicAdd(o + 3, v.w * norm);
}

// Final copy to d_out with plain vector stores.
__global__ void k_out_copy(float* __restrict__ out, int n) {
    int idx = blockIdx.x * blockDim.x + threadIdx.x;
    if (idx < n * (FIN / 4)) {
        reinterpret_cast<float4*>(out)[idx] =
            reinterpret_cast<const float4*>(g_out)[idx];
    }
}

// ---------------------------------------------------------------------------
extern "C" void kernel_launch(void* const* d_in, const int* in_sizes, int n_in,
                              void* d_out, int out_size) {
    const float* x  = (const float*)d_in[0];
    const void*  ei = d_in[1];                 // edge_index [2,E], int32 (see above)
    const float* W1 = (const float*)d_in[2];
    const float* b1 = (const float*)d_in[3];
    const float* W2 = (const float*)d_in[4];
    const float* b2 = (const float*)d_in[5];
    float*       out = (float*)d_out;

    const int N = in_sizes[0] / FIN;   // 100000
    const int E = in_sizes[1] / 2;     // 1200000 (element count is dtype-agnostic)

    const int T = 256;
    k_detect      <<<1, 256>>>((const int*)ei);
    k_deg_init    <<<(N + T - 1) / T, T>>>(N);
    k_deg_count   <<<(E + T - 1) / T, T>>>(ei, E);
    k_deg_finalize<<<(N + T - 1) / T, T>>>(N);

    k_gemm1   <<<(N + 7) / 8, T>>>(x, W1, N);
    k_a1_init <<<(N * FMID + T - 1) / T, T>>>(N);
    k_scatter1<<<(E * 8 + T - 1) / T, T>>>(ei, E);

    k_gemm2   <<<(N + 7) / 8, T>>>(b1, W2, N);
    k_out_init<<<(N * FIN + T - 1) / T, T>>>(b2, N);
    k_scatter2<<<(E * 16 + T - 1) / T, T>>>(ei, E);
    k_out_copy<<<(N * (FIN / 4) + T - 1) / T, T>>>(out, N);
}

// round 5
// speedup vs baseline: 1.6822x; 1.6822x over previous
#include <cuda_runtime.h>
#include <cstdint>

// scGNN: 2-layer GCN on GB300.
//   deg = indegree(dst)+1 ; dinv = rsqrt(deg) ; norm(e) = dinv[src]*dinv[dst]
//   L1: h1 = x@W1 ; a1 = scatter_add(h1[src]*norm -> dst) + self ; r = relu(a1+b1)
//   L2: h2 = r@W2 ; out = scatter_add(h2[src]*norm -> dst) + self + b2
//
// edge_index arrives as int32 (JAX x64-disabled); runtime dtype detection kept
// as cheap insurance. Scatters use vector red.global.add.v4.f32 (4x fewer
// LTS atomic ops than scalar; round-1..3 traps were an unrelated address bug).

#define NN   100000
#define FIN  64
#define FMID 32

static __device__ int   g_is64;
static __device__ __align__(16) float g_dinv[NN];
static __device__ __align__(16) float g_h1[NN * FMID];   // x @ W1
static __device__ __align__(16) float g_a1[NN * FMID];   // layer-1 aggregate
static __device__ __align__(16) float g_h2[NN * FIN];    // relu(a1+b1) @ W2

// ---------------------------------------------------------------------------
// Vector fire-and-forget reduction: 4 floats per LTS atomic op.
__device__ __forceinline__ void red_add_v4(float* addr, float a, float b,
                                           float c, float d) {
    asm volatile("red.global.add.v4.f32 [%0], {%1, %2, %3, %4};"
                 :: "l"(addr), "f"(a), "f"(b), "f"(c), "f"(d)
                 : "memory");
}

// Edge-index accessor: uniform branch on detected dtype + clamp (a bad index
// becomes a wrong answer, never a trap).
__device__ __forceinline__ int get_idx(const void* ei, int pos) {
    int v = g_is64 ? (int)((const long long*)ei)[pos]
                   : ((const int*)ei)[pos];
    return min(max(v, 0), NN - 1);
}

// Detect int64-vs-int32: int64 values < 2^31 have all-zero high words.
__global__ void k_detect(const int* __restrict__ ei) {
    __shared__ int nz;
    if (threadIdx.x == 0) nz = 0;
    __syncthreads();
    for (int i = threadIdx.x; i < 2048; i += blockDim.x)
        if (ei[2 * i + 1] != 0) nz = 1;
    __syncthreads();
    if (threadIdx.x == 0) g_is64 = (nz == 0) ? 1 : 0;
}

// ---------------------------------------------------------------------------
__global__ void k_deg_init(int n) {
    int i = blockIdx.x * blockDim.x + threadIdx.x;
    if (i < n) g_dinv[i] = 1.0f;   // self-loop contributes 1 to in-degree
}

__global__ void k_deg_count(const void* __restrict__ ei, int E) {
    int i = blockIdx.x * blockDim.x + threadIdx.x;
    if (i < E) atomicAdd(&g_dinv[get_idx(ei, E + i)], 1.0f);
}

__global__ void k_deg_finalize(int n) {
    int i = blockIdx.x * blockDim.x + threadIdx.x;
    if (i < n) g_dinv[i] = rsqrtf(g_dinv[i]);
}

// ---------------------------------------------------------------------------
// GEMM1 (+ fused a1 self-loop init): h1 = x@W1 ; a1 = dinv^2 * h1.
// One warp per row, lane = out col.
__global__ void k_gemm1(const float* __restrict__ x,
                        const float* __restrict__ W1, int n) {
    __shared__ float sW[FIN * FMID];  // 8 KB
    for (int i = threadIdx.x; i < FIN * FMID; i += blockDim.x)
        sW[i] = W1[i];
    __syncthreads();

    int warp = threadIdx.x >> 5;
    int lane = threadIdx.x & 31;
    int row  = blockIdx.x * 8 + warp;
    if (row >= n) return;

    float xa = x[row * FIN + lane];
    float xb = x[row * FIN + 32 + lane];
    float acc = 0.0f;
#pragma unroll
    for (int k = 0; k < 32; k++)
        acc += __shfl_sync(0xffffffffu, xa, k) * sW[k * FMID + lane];
#pragma unroll
    for (int k = 0; k < 32; k++)
        acc += __shfl_sync(0xffffffffu, xb, k) * sW[(k + 32) * FMID + lane];

    float di = g_dinv[row];
    g_h1[row * FMID + lane] = acc;
    g_a1[row * FMID + lane] = di * di * acc;   // self-loop term, full overwrite
}

// Layer-1 edge scatter: 8 threads/edge; each gathers a float4, one v4 RED.
__global__ void k_scatter1(const void* __restrict__ ei, int E) {
    int t = blockIdx.x * blockDim.x + threadIdx.x;
    if (t >= E * 8) return;
    int e = t >> 3;
    int q = (t & 7) * 4;
    int s = get_idx(ei, e);
    int d = get_idx(ei, E + e);
    float norm = g_dinv[s] * g_dinv[d];
    const float4 v = *reinterpret_cast<const float4*>(&g_h1[s * FMID + q]);
    red_add_v4(&g_a1[d * FMID + q],
               v.x * norm, v.y * norm, v.z * norm, v.w * norm);
}

// ---------------------------------------------------------------------------
// GEMM2 (fused relu+bias in, fused out init): h2 = relu(a1+b1)@W2 ;
// out = b2 + dinv^2 * h2 (full overwrite of the poisoned d_out).
__global__ void k_gemm2(const float* __restrict__ b1,
                        const float* __restrict__ W2,
                        const float* __restrict__ b2,
                        float* __restrict__ out, int n) {
    __shared__ float sW[FMID * FIN];  // 8 KB
    for (int i = threadIdx.x; i < FMID * FIN; i += blockDim.x)
        sW[i] = W2[i];
    __syncthreads();

    int warp = threadIdx.x >> 5;
    int lane = threadIdx.x & 31;
    int row  = blockIdx.x * 8 + warp;
    if (row >= n) return;

    float a = fmaxf(g_a1[row * FMID + lane] + b1[lane], 0.0f);
    float acc0 = 0.0f, acc1 = 0.0f;
#pragma unroll
    for (int k = 0; k < 32; k++) {
        float ak = __shfl_sync(0xffffffffu, a, k);
        acc0 += ak * sW[k * FIN + lane];
        acc1 += ak * sW[k * FIN + 32 + lane];
    }
    float di  = g_dinv[row];
    float di2 = di * di;
    g_h2[row * FIN + lane]       = acc0;
    g_h2[row * FIN + 32 + lane]  = acc1;
    out[row * FIN + lane]        = b2[lane]      + di2 * acc0;
    out[row * FIN + 32 + lane]   = b2[32 + lane] + di2 * acc1;
}

// Layer-2 edge scatter: 16 threads/edge, one v4 RED each, directly into d_out.
__global__ void k_scatter2(const void* __restrict__ ei,
                           float* __restrict__ out, int E) {
    int t = blockIdx.x * blockDim.x + threadIdx.x;
    if (t >= E * 16) return;
    int e = t >> 4;
    int q = (t & 15) * 4;
    int s = get_idx(ei, e);
    int d = get_idx(ei, E + e);
    float norm = g_dinv[s] * g_dinv[d];
    const float4 v = *reinterpret_cast<const float4*>(&g_h2[s * FIN + q]);
    red_add_v4(&out[d * FIN + q],
               v.x * norm, v.y * norm, v.z * norm, v.w * norm);
}

// ---------------------------------------------------------------------------
extern "C" void kernel_launch(void* const* d_in, const int* in_sizes, int n_in,
                              void* d_out, int out_size) {
    const float* x  = (const float*)d_in[0];
    const void*  ei = d_in[1];                 // edge_index [2,E], int32
    const float* W1 = (const float*)d_in[2];
    const float* b1 = (const float*)d_in[3];
    const float* W2 = (const float*)d_in[4];
    const float* b2 = (const float*)d_in[5];
    float*       out = (float*)d_out;

    const int N = in_sizes[0] / FIN;   // 100000
    const int E = in_sizes[1] / 2;     // 1200000

    const int T = 256;
    k_detect      <<<1, 256>>>((const int*)ei);
    k_deg_init    <<<(N + T - 1) / T, T>>>(N);
    k_deg_count   <<<(E + T - 1) / T, T>>>(ei, E);
    k_deg_finalize<<<(N + T - 1) / T, T>>>(N);

    k_gemm1   <<<(N + 7) / 8, T>>>(x, W1, N);
    k_scatter1<<<(E * 8 + T - 1) / T, T>>>(ei, E);

    k_gemm2   <<<(N + 7) / 8, T>>>(b1, W2, b2, out, N);
    k_scatter2<<<(E * 16 + T - 1) / T, T>>>(ei, out, E);
}

// round 7
// speedup vs baseline: 1.8264x; 1.0857x over previous
#include <cuda_runtime.h>
#include <cstdint>

// scGNN: 2-layer GCN on GB300.
//   A = sym-normalized adjacency with self-loops.
//   out = A·relu(A·(x@W1) + b1) @ W2 + b2
// Key algebraic move: layer-2 aggregation commutes with the linear map,
//   A·(r@W2) = (A·r)@W2, so BOTH scatters run in the 32-wide space.
// NOTE: scatter buffers are selected INSIDE the kernel (device-code symbol
// resolution); passing __device__ globals as host-side args was the R6 bug.

#define NN   100000
#define EE   1200000
#define FIN  64
#define FMID 32

static __device__ int   g_is64;
static __device__ __align__(16) float g_dinv[NN];
static __device__ __align__(16) int2  g_sd[EE];          // clamped (src,dst)
static __device__ __align__(16) float g_norm[EE];        // dinv[s]*dinv[d]
static __device__ __align__(16) float g_h1[NN * FMID];   // x @ W1
static __device__ __align__(16) float g_a1[NN * FMID];   // layer-1 aggregate
static __device__ __align__(16) float g_r [NN * FMID];   // relu(a1+b1)
static __device__ __align__(16) float g_a2[NN * FMID];   // layer-2 aggregate (pre-GEMM)

// ---------------------------------------------------------------------------
__device__ __forceinline__ void red_add_v4(float* addr, float a, float b,
                                           float c, float d) {
    asm volatile("red.global.add.v4.f32 [%0], {%1, %2, %3, %4};"
                 :: "l"(addr), "f"(a), "f"(b), "f"(c), "f"(d)
                 : "memory");
}

__device__ __forceinline__ int get_idx(const void* ei, int pos) {
    int v = g_is64 ? (int)((const long long*)ei)[pos]
                   : ((const int*)ei)[pos];
    return min(max(v, 0), NN - 1);
}

// ---------------------------------------------------------------------------
// dinv := 1 (self-loop) ; block 0 also detects edge-index dtype.
__global__ void k_init(const int* __restrict__ ei, int n) {
    int i = blockIdx.x * blockDim.x + threadIdx.x;
    if (i < n) g_dinv[i] = 1.0f;
    if (blockIdx.x == 0) {
        __shared__ int nz;
        if (threadIdx.x == 0) nz = 0;
        __syncthreads();
        for (int k = threadIdx.x; k < 2048; k += blockDim.x)
            if (ei[2 * k + 1] != 0) nz = 1;
        __syncthreads();
        if (threadIdx.x == 0) g_is64 = (nz == 0) ? 1 : 0;
    }
}

// Decode+clamp edge endpoints once; fused in-degree histogram.
__global__ void k_edge_prep(const void* __restrict__ ei, int E) {
    int e = blockIdx.x * blockDim.x + threadIdx.x;
    if (e >= E) return;
    int s = get_idx(ei, e);
    int d = get_idx(ei, E + e);
    g_sd[e] = make_int2(s, d);
    atomicAdd(&g_dinv[d], 1.0f);
}

__global__ void k_deg_finalize(int n) {
    int i = blockIdx.x * blockDim.x + threadIdx.x;
    if (i < n) g_dinv[i] = rsqrtf(g_dinv[i]);
}

__global__ void k_norm(int E) {
    int e = blockIdx.x * blockDim.x + threadIdx.x;
    if (e >= E) return;
    int2 sd = g_sd[e];
    g_norm[e] = g_dinv[sd.x] * g_dinv[sd.y];
}

// ---------------------------------------------------------------------------
// GEMM1 (+ fused a1 self-loop init): h1 = x@W1 ; a1 = dinv^2 * h1.
__global__ void k_gemm1(const float* __restrict__ x,
                        const float* __restrict__ W1, int n) {
    __shared__ float sW[FIN * FMID];  // 8 KB
    for (int i = threadIdx.x; i < FIN * FMID; i += blockDim.x)
        sW[i] = W1[i];
    __syncthreads();

    int warp = threadIdx.x >> 5;
    int lane = threadIdx.x & 31;
    int row  = blockIdx.x * 8 + warp;
    if (row >= n) return;

    float xa = x[row * FIN + lane];
    float xb = x[row * FIN + 32 + lane];
    float acc = 0.0f;
#pragma unroll
    for (int k = 0; k < 32; k++)
        acc += __shfl_sync(0xffffffffu, xa, k) * sW[k * FMID + lane];
#pragma unroll
    for (int k = 0; k < 32; k++)
        acc += __shfl_sync(0xffffffffu, xb, k) * sW[(k + 32) * FMID + lane];

    float di = g_dinv[row];
    g_h1[row * FMID + lane] = acc;
    g_a1[row * FMID + lane] = di * di * acc;
}

// 32-wide edge scatter: 4 threads/edge, 8 floats each (2 v4 REDs).
// which=0: g_h1 -> g_a1 (layer 1)   which=1: g_r -> g_a2 (layer 2)
// Buffers resolved in device code (never passed from host).
__global__ void k_scatter32(int which, int E) {
    int t = blockIdx.x * blockDim.x + threadIdx.x;
    if (t >= E * 4) return;
    const float* __restrict__ src = which ? g_r  : g_h1;
    float*       __restrict__ dst = which ? g_a2 : g_a1;
    int e = t >> 2;
    int q = (t & 3) * 8;
    int2  sd = g_sd[e];
    float nm = g_norm[e];
    const float4* vp = reinterpret_cast<const float4*>(&src[sd.x * FMID + q]);
    float4 v0 = vp[0];
    float4 v1 = vp[1];
    float* o = &dst[sd.y * FMID + q];
    red_add_v4(o,     v0.x * nm, v0.y * nm, v0.z * nm, v0.w * nm);
    red_add_v4(o + 4, v1.x * nm, v1.y * nm, v1.z * nm, v1.w * nm);
}

// r := relu(a1 + b1) ; a2 := dinv^2 * r (self-loop init). float4-vectorized.
__global__ void k_relu(const float* __restrict__ b1, int n) {
    int idx = blockIdx.x * blockDim.x + threadIdx.x;   // n*8 float4 slots
    if (idx >= n * (FMID / 4)) return;
    int i = idx >> 3;
    int c = (idx & 7) * 4;
    float di  = g_dinv[i];
    float di2 = di * di;
    float4 a = reinterpret_cast<const float4*>(g_a1)[idx];
    float4 bb = *reinterpret_cast<const float4*>(&b1[c]);
    float4 r;
    r.x = fmaxf(a.x + bb.x, 0.0f);
    r.y = fmaxf(a.y + bb.y, 0.0f);
    r.z = fmaxf(a.z + bb.z, 0.0f);
    r.w = fmaxf(a.w + bb.w, 0.0f);
    reinterpret_cast<float4*>(g_r)[idx] = r;
    float4 s = make_float4(di2 * r.x, di2 * r.y, di2 * r.z, di2 * r.w);
    reinterpret_cast<float4*>(g_a2)[idx] = s;
}

// GEMM2: out = a2 @ W2 + b2.  One warp per row; lane owns cols {lane, lane+32}.
__global__ void k_gemm2(const float* __restrict__ W2,
                        const float* __restrict__ b2,
                        float* __restrict__ out, int n) {
    __shared__ float sW[FMID * FIN];  // 8 KB
    for (int i = threadIdx.x; i < FMID * FIN; i += blockDim.x)
        sW[i] = W2[i];
    __syncthreads();

    int warp = threadIdx.x >> 5;
    int lane = threadIdx.x & 31;
    int row  = blockIdx.x * 8 + warp;
    if (row >= n) return;

    float a = g_a2[row * FMID + lane];
    float acc0 = 0.0f, acc1 = 0.0f;
#pragma unroll
    for (int k = 0; k < 32; k++) {
        float ak = __shfl_sync(0xffffffffu, a, k);
        acc0 += ak * sW[k * FIN + lane];
        acc1 += ak * sW[k * FIN + 32 + lane];
    }
    out[row * FIN + lane]      = acc0 + b2[lane];
    out[row * FIN + 32 + lane] = acc1 + b2[32 + lane];
}

// ---------------------------------------------------------------------------
extern "C" void kernel_launch(void* const* d_in, const int* in_sizes, int n_in,
                              void* d_out, int out_size) {
    const float* x  = (const float*)d_in[0];
    const void*  ei = d_in[1];                 // edge_index [2,E], int32
    const float* W1 = (const float*)d_in[2];
    const float* b1 = (const float*)d_in[3];
    const float* W2 = (const float*)d_in[4];
    const float* b2 = (const float*)d_in[5];
    float*       out = (float*)d_out;

    const int N = in_sizes[0] / FIN;   // 100000
    const int E = in_sizes[1] / 2;     // 1200000

    const int T = 256;
    k_init        <<<(N + T - 1) / T, T>>>((const int*)ei, N);
    k_edge_prep   <<<(E + T - 1) / T, T>>>(ei, E);
    k_deg_finalize<<<(N + T - 1) / T, T>>>(N);
    k_norm        <<<(E + T - 1) / T, T>>>(E);

    k_gemm1    <<<(N + 7) / 8, T>>>(x, W1, N);
    k_scatter32<<<(E * 4 + T - 1) / T, T>>>(0, E);

    k_relu     <<<(N * (FMID / 4) + T - 1) / T, T>>>(b1, N);
    k_scatter32<<<(E * 4 + T - 1) / T, T>>>(1, E);

    k_gemm2    <<<(N + 7) / 8, T>>>(W2, b2, out, N);
}